// round 15
// baseline (speedup 1.0000x reference)
#include <cuda_runtime.h>
#include <cuda_fp16.h>
#include <math.h>
#include <stdint.h>

#define NQ   32768
#define MOFF 27

// smem: A region (131 rows x 128B fp16) + 2 B buffers (16KB) + biases
#define ARH    0
#define BB0    16768
#define BB1    33152
#define BIASK  49536     // 27*64 fp32 = 6912B
#define BIASV  56448
#define BIASQ  63360
#define SMEMB  63616     // -> 3 CTAs/SM (smem), 84-reg cap -> 3 CTAs (regs)

// Scratch (static device globals: allocation-free per harness rules)
__device__ float g_h0[NQ * 64];
__device__ float g_h1[NQ * 64];
__device__ __half g_hf0[NQ * 64];
__device__ __half g_hf1[NQ * 64];
__device__ float g_stats[8];
__device__ unsigned g_wq_ph[2 * 2048];
__device__ unsigned g_wkv_ph[54 * 4096];

// ---------------------------------------------------------------------------
__device__ __forceinline__ uint32_t smem_u32(const void* p) {
    uint32_t a;
    asm("{ .reg .u64 t; cvta.to.shared.u64 t, %1; cvt.u32.u64 %0, t; }" : "=r"(a) : "l"(p));
    return a;
}
__device__ __forceinline__ void cpa16z(uint32_t dst, const void* src, int ok) {
    asm volatile("cp.async.cg.shared.global [%0], [%1], 16, %2;"
                 :: "r"(dst), "l"(src), "r"(ok ? 16 : 0));
}
__device__ __forceinline__ void cpa16(uint32_t dst, const void* src) {
    asm volatile("cp.async.cg.shared.global [%0], [%1], 16;" :: "r"(dst), "l"(src));
}
#define CPA_COMMIT() asm volatile("cp.async.commit_group;" ::: "memory")
#define CPA_WAIT0()  asm volatile("cp.async.wait_group 0;"  ::: "memory")

__device__ __forceinline__ void lds128u(unsigned* v, uint32_t a) {
    asm volatile("ld.shared.v4.b32 {%0, %1, %2, %3}, [%4];"
                 : "=r"(v[0]), "=r"(v[1]), "=r"(v[2]), "=r"(v[3]) : "r"(a));
}
__device__ __forceinline__ float2 lds64f(uint32_t a) {
    float2 v;
    asm volatile("ld.shared.v2.f32 {%0, %1}, [%2];" : "=f"(v.x), "=f"(v.y) : "r"(a));
    return v;
}
__device__ __forceinline__ void ldsm4(unsigned* r, uint32_t a) {
    asm volatile("ldmatrix.sync.aligned.m8n8.x4.shared.b16 {%0, %1, %2, %3}, [%4];"
                 : "=r"(r[0]), "=r"(r[1]), "=r"(r[2]), "=r"(r[3]) : "r"(a));
}
__device__ __forceinline__ void mma16(float* d, const unsigned* a, unsigned b0, unsigned b1) {
    asm volatile(
        "mma.sync.aligned.m16n8k16.row.col.f32.f16.f16.f32 "
        "{%0,%1,%2,%3}, {%4,%5,%6,%7}, {%8,%9}, {%0,%1,%2,%3};"
        : "+f"(d[0]), "+f"(d[1]), "+f"(d[2]), "+f"(d[3])
        : "r"(a[0]), "r"(a[1]), "r"(a[2]), "r"(a[3]), "r"(b0), "r"(b1));
}
__device__ __forceinline__ unsigned packh2(float x, float y) {
    __half2 t = __floats2half2_rn(x, y);
    return *reinterpret_cast<unsigned*>(&t);
}
__device__ __forceinline__ float2 unpackh2(unsigned u) {
    __half2 t = *reinterpret_cast<__half2*>(&u);
    return __half22float2(t);
}

// ---------------------------------------------------------------------------
// 0) Weight repack to lds128 fragment layout.
// ---------------------------------------------------------------------------
__global__ void repack_w_kernel(const float* __restrict__ Wq,
                                const float* __restrict__ Wk,
                                const float* __restrict__ Wv) {
    int idx = blockIdx.x * 256 + threadIdx.x;
    if (idx >= 54 * 2048) return;
    int mi = idx >> 11, e = idx & 2047;
    int cg = e >> 9, ks = (e >> 7) & 3, lane = (e >> 2) & 31, u = e & 3;
    int cin  = 16 * ks + 2 * (lane & 3) + 8 * (u & 1);
    int cout = 16 * cg + 8 * (u >> 1) + (lane >> 2);
    int s0 = mi * 4096 + cin * 64 + cout;
    g_wkv_ph[mi * 4096 + e]        = packh2(Wk[s0], Wk[s0 + 64]);
    g_wkv_ph[mi * 4096 + 2048 + e] = packh2(Wv[s0], Wv[s0 + 64]);
    if (mi < 2)
        g_wq_ph[mi * 2048 + e] = packh2(Wq[s0], Wq[s0 + 64]);
}

// ---------------------------------------------------------------------------
// 1) BatchNorm batch statistics
// ---------------------------------------------------------------------------
__global__ void bn_stats_kernel(const float* __restrict__ x) {
    float s0 = 0.f, s1 = 0.f, s2 = 0.f, t0 = 0.f, t1 = 0.f, t2 = 0.f;
    for (int p = threadIdx.x; p < NQ; p += 1024) {
        float v0 = x[p * 3 + 0], v1 = x[p * 3 + 1], v2 = x[p * 3 + 2];
        s0 += v0; s1 += v1; s2 += v2;
        t0 += v0 * v0; t1 += v1 * v1; t2 += v2 * v2;
    }
#pragma unroll
    for (int o = 16; o; o >>= 1) {
        s0 += __shfl_xor_sync(0xffffffffu, s0, o);
        s1 += __shfl_xor_sync(0xffffffffu, s1, o);
        s2 += __shfl_xor_sync(0xffffffffu, s2, o);
        t0 += __shfl_xor_sync(0xffffffffu, t0, o);
        t1 += __shfl_xor_sync(0xffffffffu, t1, o);
        t2 += __shfl_xor_sync(0xffffffffu, t2, o);
    }
    __shared__ float red[32][6];
    int lane = threadIdx.x & 31, w = threadIdx.x >> 5;
    if (lane == 0) {
        red[w][0] = s0; red[w][1] = s1; red[w][2] = s2;
        red[w][3] = t0; red[w][4] = t1; red[w][5] = t2;
    }
    __syncthreads();
    if (threadIdx.x < 32) {
        float a0 = red[lane][0], a1 = red[lane][1], a2 = red[lane][2];
        float a3 = red[lane][3], a4 = red[lane][4], a5 = red[lane][5];
#pragma unroll
        for (int o = 16; o; o >>= 1) {
            a0 += __shfl_xor_sync(0xffffffffu, a0, o);
            a1 += __shfl_xor_sync(0xffffffffu, a1, o);
            a2 += __shfl_xor_sync(0xffffffffu, a2, o);
            a3 += __shfl_xor_sync(0xffffffffu, a3, o);
            a4 += __shfl_xor_sync(0xffffffffu, a4, o);
            a5 += __shfl_xor_sync(0xffffffffu, a5, o);
        }
        if (lane == 0) {
            const float inv = 1.0f / (float)NQ;
            float m0 = a0 * inv, m1 = a1 * inv, m2 = a2 * inv;
            g_stats[0] = m0; g_stats[1] = m1; g_stats[2] = m2;
            g_stats[4] = rsqrtf(a3 * inv - m0 * m0 + 1e-5f);
            g_stats[5] = rsqrtf(a4 * inv - m1 * m1 + 1e-5f);
            g_stats[6] = rsqrtf(a5 * inv - m2 * m2 + 1e-5f);
        }
    }
}

// ---------------------------------------------------------------------------
// 2) h0 = normalize(x) @ W_in + b_in
// ---------------------------------------------------------------------------
__global__ void input_proj_kernel(const float* __restrict__ x,
                                  const float* __restrict__ W_in,
                                  const float* __restrict__ b_in,
                                  float* __restrict__ h_out,
                                  __half* __restrict__ hf_out) {
    int idx = blockIdx.x * 256 + threadIdx.x;
    int p = idx >> 6, c = idx & 63;
    float acc = b_in[c];
#pragma unroll
    for (int f = 0; f < 3; f++) {
        float xn = (x[p * 3 + f] - g_stats[f]) * g_stats[4 + f];
        acc += xn * W_in[f * 64 + c];
    }
    h_out[idx] = acc;
    hf_out[idx] = __float2half_rn(acc);
}

// ---------------------------------------------------------------------------
// staging
// ---------------------------------------------------------------------------
__device__ __forceinline__ void stage_region(uint32_t sb, const __half* hf,
                                             int pos_rb, int tid) {
    for (int u = tid; u < 1048; u += 256) {     // 131 rows x 8 chunks
        int r = u >> 3, c4 = u & 7;
        uint32_t dst = sb + (r << 7) + ((c4 ^ (r & 7)) << 4);
        int pos = pos_rb + r;
        int ok = (unsigned)pos < (unsigned)NQ;
        cpa16z(dst, hf + (size_t)(ok ? pos : 0) * 64 + c4 * 8, ok);
    }
}
__device__ __forceinline__ void stage_B(uint32_t dst, const unsigned* w, int tid) {
#pragma unroll
    for (int i = 0; i < 4; i++) {
        int u = tid + (i << 8);             // 0..1023 (16KB)
        cpa16(dst + (u << 4), w + (u << 2));
    }
}

// ---------------------------------------------------------------------------
// 3) Fused attention. 512 CTAs x 64-query tiles, 8 warps: warp tile 32 rows
//    x 16 ch (rg = w&1 row-half, cg = w>>1 head). K and V sweeps separate
//    (A frags reloaded) to keep live registers under the 84-reg / 3-CTA cap.
// ---------------------------------------------------------------------------
__global__ __launch_bounds__(256, 3)
void attn_kernel(const float* __restrict__ h_in, const __half* __restrict__ hf,
                 float* __restrict__ h_out, __half* __restrict__ hfo,
                 const unsigned* __restrict__ wq_ph, const float* __restrict__ bq,
                 const unsigned* __restrict__ wkv_ph,
                 const float* __restrict__ bk, const float* __restrict__ bv) {
    extern __shared__ char smem[];
    const uint32_t sb = smem_u32(smem);
    const int tid  = threadIdx.x;
    const int lane = tid & 31;
    const int w    = tid >> 5;
    const int tig  = lane & 3;
    const int l4   = lane >> 2;
    const int rg   = w & 1;
    const int cg   = w >> 1;
    const int lrow = lane & 15;
    const int lhi  = lane >> 4;

    const int bx    = blockIdx.x;
    const int tbase = bx << 6;                  // 64 queries per CTA
    const int a0    = (bx & 15) << 1;           // 2 a-rows per tile
    const uint32_t bKoff = (uint32_t)(cg << 11) + (uint32_t)(lane << 4);
    const uint32_t biasOff = (uint32_t)((cg << 6) + (tig << 3));

    // ---- prologue: region(dt=0), Wq -> BB1, biases, B[m=9] -> BB0 ----
    stage_region(sb, hf, tbase - 33, tid);
    for (int u = tid; u < 880; u += 256) {
        if (u < 432)      cpa16(sb + BIASK + (u << 4), bk + (u << 2));
        else if (u < 864) cpa16(sb + BIASV + ((u - 432) << 4), bv + ((u - 432) << 2));
        else              cpa16(sb + BIASQ + ((u - 864) << 4), bq + ((u - 864) << 2));
    }
    for (int u = tid; u < 512; u += 256)
        cpa16(sb + BB1 + (u << 4), wq_ph + (u << 2));
    stage_B(sb + BB0, wkv_ph + 9 * 4096, tid);
    CPA_COMMIT(); CPA_WAIT0();
    __syncthreads();

    // ---- Q projection (rows at region-local base 33 + rg*32) ----
    unsigned qp[8];
    {
        int rl = 33 + (rg << 5) + lrow;
        uint32_t abase = sb + (rl << 7);
        int xs = rl & 7;
        float qf[16];
#pragma unroll
        for (int e = 0; e < 16; e++) qf[e] = 0.0f;
#pragma unroll
        for (int ks = 0; ks < 4; ks++) {
            unsigned bf[4];
            lds128u(bf, sb + BB1 + bKoff + (ks << 9));
#pragma unroll
            for (int mt = 0; mt < 2; mt++) {
                unsigned a[4];
                ldsm4(a, abase + (mt << 11) + ((unsigned)(((2 * ks + lhi) ^ xs)) << 4));
                mma16(&qf[mt * 8 + 0], a, bf[0], bf[1]);
                mma16(&qf[mt * 8 + 4], a, bf[2], bf[3]);
            }
        }
        float2 bq0 = lds64f(sb + BIASQ + biasOff);
        float2 bq1 = lds64f(sb + BIASQ + biasOff + 32);
#pragma unroll
        for (int mt = 0; mt < 2; mt++)
#pragma unroll
            for (int j = 0; j < 2; j++) {
                float2 b2 = j ? bq1 : bq0;
#pragma unroll
                for (int rh = 0; rh < 2; rh++)
                    qp[(mt * 2 + j) * 2 + rh] =
                        packh2(qf[(mt * 2 + j) * 4 + rh * 2 + 0] + b2.x,
                               qf[(mt * 2 + j) * 4 + rh * 2 + 1] + b2.y);
            }
    }

    // ---- spatial validity masks (4 rows per lane) ----
    unsigned vm[4];
#pragma unroll
    for (int t = 0; t < 4; t++) {
        int lr = (rg << 5) + ((t >> 1) << 4) + ((t & 1) << 3) + l4;
        int ga = a0 + (lr >> 5), gb = lr & 31;
        bool aM = (ga > 0), aP = (ga < 31), bM = (gb > 0), bP = (gb < 31);
        unsigned v = 0;
#pragma unroll
        for (int m = 0; m < MOFF; m++) {
            int r9 = m % 9;
            int di = r9 / 3 - 1, dj = r9 % 3 - 1;
            bool ok = (di < 0 ? aM : (di > 0 ? aP : true)) &&
                      (dj < 0 ? bM : (dj > 0 ? bP : true));
            v |= ((unsigned)ok) << m;
        }
        vm[t] = v;
    }

    float acc[16], den[4];
#pragma unroll
    for (int e = 0; e < 16; e++) acc[e] = 0.0f;
#pragma unroll
    for (int t = 0; t < 4; t++) den[t] = 0.0f;

    // ---- 27-offset mainloop (dt-grouped: 9..17, 0..8, 18..26) ----
#pragma unroll 1
    for (int i = 0; i < MOFF; i++) {
        int m = i + (i < 9 ? 9 : (i < 18 ? -9 : 0));
        CPA_WAIT0();
        __syncthreads();
        if (i < 26) {
            int mn = i + 1;
            mn += (mn < 9 ? 9 : (mn < 18 ? -9 : 0));
            stage_B(sb + ((i & 1) ? BB0 : BB1), wkv_ph + mn * 4096, tid);
            CPA_COMMIT();
        }
        const uint32_t bB = sb + ((i & 1) ? BB1 : BB0);
        int r9 = m % 9;
        int di = r9 / 3 - 1, dj = r9 % 3 - 1;
        int rl = 33 + di * 32 + dj + (rg << 5) + lrow;
        uint32_t abase = sb + (rl << 7);
        int xs = rl & 7;

        float p[4];
        {
            // K sweep
            float dK[16];
#pragma unroll
            for (int e = 0; e < 16; e++) dK[e] = 0.0f;
#pragma unroll
            for (int ks = 0; ks < 4; ks++) {
                unsigned bkf[4];
                lds128u(bkf, bB + bKoff + (ks << 9));
#pragma unroll
                for (int mt = 0; mt < 2; mt++) {
                    unsigned a[4];
                    ldsm4(a, abase + (mt << 11) +
                              ((unsigned)(((2 * ks + lhi) ^ xs)) << 4));
                    mma16(&dK[mt * 8 + 0], a, bkf[0], bkf[1]);
                    mma16(&dK[mt * 8 + 4], a, bkf[2], bkf[3]);
                }
            }
            // scores
            float2 bk0 = lds64f(sb + BIASK + (m << 8) + biasOff);
            float2 bk1 = lds64f(sb + BIASK + (m << 8) + biasOff + 32);
            float sp[4];
#pragma unroll
            for (int t = 0; t < 4; t++) sp[t] = 0.0f;
#pragma unroll
            for (int mt = 0; mt < 2; mt++)
#pragma unroll
                for (int j = 0; j < 2; j++) {
                    float2 b2 = j ? bk1 : bk0;
#pragma unroll
                    for (int rh = 0; rh < 2; rh++) {
                        float2 qv = unpackh2(qp[(mt * 2 + j) * 2 + rh]);
                        float k0 = dK[(mt * 2 + j) * 4 + rh * 2 + 0] + b2.x;
                        float k1 = dK[(mt * 2 + j) * 4 + rh * 2 + 1] + b2.y;
                        sp[mt * 2 + rh] += k0 * qv.x + k1 * qv.y;
                    }
                }
#pragma unroll
            for (int t = 0; t < 4; t++) {
                float s = sp[t];
                s += __shfl_xor_sync(0xffffffffu, s, 1);
                s += __shfl_xor_sync(0xffffffffu, s, 2);
                bool ok = (vm[t] >> m) & 1u;
                float pv = __expf(ok ? s : -1e30f);
                p[t] = pv;
                den[t] += pv;
            }
        }
        {
            // V sweep (A frags reloaded; dK registers dead -> reused)
            float dV[16];
#pragma unroll
            for (int e = 0; e < 16; e++) dV[e] = 0.0f;
#pragma unroll
            for (int ks = 0; ks < 4; ks++) {
                unsigned bvf[4];
                lds128u(bvf, bB + 8192u + bKoff + (ks << 9));
#pragma unroll
                for (int mt = 0; mt < 2; mt++) {
                    unsigned a[4];
                    ldsm4(a, abase + (mt << 11) +
                              ((unsigned)(((2 * ks + lhi) ^ xs)) << 4));
                    mma16(&dV[mt * 8 + 0], a, bvf[0], bvf[1]);
                    mma16(&dV[mt * 8 + 4], a, bvf[2], bvf[3]);
                }
            }
            float2 bv0 = lds64f(sb + BIASV + (m << 8) + biasOff);
            float2 bv1 = lds64f(sb + BIASV + (m << 8) + biasOff + 32);
#pragma unroll
            for (int mt = 0; mt < 2; mt++)
#pragma unroll
                for (int j = 0; j < 2; j++) {
                    float2 b2 = j ? bv1 : bv0;
#pragma unroll
                    for (int rh = 0; rh < 2; rh++) {
                        float pw = p[mt * 2 + rh];
                        acc[(mt * 2 + j) * 4 + rh * 2 + 0] +=
                            pw * (dV[(mt * 2 + j) * 4 + rh * 2 + 0] + b2.x);
                        acc[(mt * 2 + j) * 4 + rh * 2 + 1] +=
                            pw * (dV[(mt * 2 + j) * 4 + rh * 2 + 1] + b2.y);
                    }
                }
        }

        if (i == 8 || i == 17) {
            __syncthreads();          // all region reads complete
            int dt = (i == 8) ? -1 : 1;
            stage_region(sb, hf, tbase + dt * 1024 - 33, tid);
            CPA_COMMIT();
        }
    }

    // ---- epilogue ----
#pragma unroll
    for (int mt = 0; mt < 2; mt++)
#pragma unroll
        for (int rh = 0; rh < 2; rh++) {
            int pos = tbase + (rg << 5) + (mt << 4) + (rh << 3) + l4;
            float iv = 1.0f / den[mt * 2 + rh];
            const float* rp = h_in + ((size_t)pos << 6);
            float* op = h_out + ((size_t)pos << 6);
#pragma unroll
            for (int j = 0; j < 2; j++) {
                int c = 16 * cg + 8 * j + 2 * tig;
                float2 r = *(const float2*)(rp + c);
                float ox = acc[(mt * 2 + j) * 4 + rh * 2 + 0] * iv + r.x;
                float oy = acc[(mt * 2 + j) * 4 + rh * 2 + 1] * iv + r.y;
                float2 o; o.x = ox; o.y = oy;
                *(float2*)(op + c) = o;
                if (hfo) {
                    __half2 h2 = __floats2half2_rn(ox, oy);
                    *(unsigned*)(&hfo[(size_t)pos * 64 + c]) = *(unsigned*)&h2;
                }
            }
        }
}

// ---------------------------------------------------------------------------
// 4) out = h @ W_out + b_out
// ---------------------------------------------------------------------------
__global__ void out_proj_kernel(const float* __restrict__ h,
                                const float* __restrict__ W_out,
                                const float* __restrict__ b_out,
                                float* __restrict__ out) {
    __shared__ float hs[32 * 64];
    int tid = threadIdx.x;
    int base = blockIdx.x * 32;
    for (int j = tid; j < 2048; j += 128) hs[j] = h[base * 64 + j];
    __syncthreads();
    if (tid < 96) {
        int rr = tid / 3, f = tid - 3 * (tid / 3);
        float acc = b_out[f];
#pragma unroll 8
        for (int cp = 0; cp < 64; cp++)
            acc += hs[rr * 64 + cp] * W_out[cp * 3 + f];
        out[(base + rr) * 3 + f] = acc;
    }
}

// ---------------------------------------------------------------------------
extern "C" void kernel_launch(void* const* d_in, const int* in_sizes, int n_in,
                              void* d_out, int out_size) {
    const float* x     = (const float*)d_in[0];
    const float* W_in  = (const float*)d_in[1];
    const float* b_in  = (const float*)d_in[2];
    const float* W_out = (const float*)d_in[3];
    const float* b_out = (const float*)d_in[4];
    const float* Wq    = (const float*)d_in[5];
    const float* bq    = (const float*)d_in[6];
    const float* Wk    = (const float*)d_in[7];
    const float* bk    = (const float*)d_in[8];
    const float* Wv    = (const float*)d_in[9];
    const float* bv    = (const float*)d_in[10];
    float* out = (float*)d_out;

    float *h0, *h1;
    __half *hf0, *hf1;
    unsigned *wq_ph, *wkv_ph;
    cudaGetSymbolAddress((void**)&h0, g_h0);
    cudaGetSymbolAddress((void**)&h1, g_h1);
    cudaGetSymbolAddress((void**)&hf0, g_hf0);
    cudaGetSymbolAddress((void**)&hf1, g_hf1);
    cudaGetSymbolAddress((void**)&wq_ph, g_wq_ph);
    cudaGetSymbolAddress((void**)&wkv_ph, g_wkv_ph);
    cudaFuncSetAttribute(attn_kernel, cudaFuncAttributeMaxDynamicSharedMemorySize, SMEMB);

    repack_w_kernel<<<(54 * 2048 + 255) / 256, 256>>>(Wq, Wk, Wv);
    bn_stats_kernel<<<1, 1024>>>(x);
    input_proj_kernel<<<(NQ * 64) / 256, 256>>>(x, W_in, b_in, h0, hf0);

    attn_kernel<<<512, 256, SMEMB>>>(h0, hf0, h1, hf1,
        wq_ph, bq, wkv_ph, bk, bv);
    attn_kernel<<<512, 256, SMEMB>>>(h1, hf1, h0, (__half*)nullptr,
        wq_ph + 2048, bq + 64, wkv_ph + 27 * 4096, bk + 27 * 64, bv + 27 * 64);

    out_proj_kernel<<<NQ / 32, 128>>>(h0, W_out, b_out, out);
}

// round 16
// speedup vs baseline: 1.1451x; 1.1451x over previous
#include <cuda_runtime.h>
#include <cuda_fp16.h>
#include <math.h>
#include <stdint.h>

#define NQ   32768
#define MOFF 27

// smem: A region (195 rows x 128B fp16) + 2 B buffers (16KB) + biases
#define ARH    0
#define BB0    24960
#define BB1    41344
#define BIASK  57728     // 27*64 fp32 = 6912B
#define BIASV  64640
#define BIASQ  71552
#define SMEMB  71808

// Scratch (static device globals: allocation-free per harness rules)
__device__ float g_h0[NQ * 64];
__device__ float g_h1[NQ * 64];
__device__ __half g_hf0[NQ * 64];
__device__ __half g_hf1[NQ * 64];
__device__ float g_stats[8];
__device__ float g_part[64 * 6];
__device__ unsigned g_wq_ph[2 * 2048];
__device__ unsigned g_wkv_ph[54 * 4096];

// ---------------------------------------------------------------------------
__device__ __forceinline__ uint32_t smem_u32(const void* p) {
    uint32_t a;
    asm("{ .reg .u64 t; cvta.to.shared.u64 t, %1; cvt.u32.u64 %0, t; }" : "=r"(a) : "l"(p));
    return a;
}
__device__ __forceinline__ void cpa16z(uint32_t dst, const void* src, int ok) {
    asm volatile("cp.async.cg.shared.global [%0], [%1], 16, %2;"
                 :: "r"(dst), "l"(src), "r"(ok ? 16 : 0));
}
__device__ __forceinline__ void cpa16(uint32_t dst, const void* src) {
    asm volatile("cp.async.cg.shared.global [%0], [%1], 16;" :: "r"(dst), "l"(src));
}
#define CPA_COMMIT() asm volatile("cp.async.commit_group;" ::: "memory")
#define CPA_WAIT0()  asm volatile("cp.async.wait_group 0;"  ::: "memory")

__device__ __forceinline__ void lds128u(unsigned* v, uint32_t a) {
    asm volatile("ld.shared.v4.b32 {%0, %1, %2, %3}, [%4];"
                 : "=r"(v[0]), "=r"(v[1]), "=r"(v[2]), "=r"(v[3]) : "r"(a));
}
__device__ __forceinline__ float2 lds64f(uint32_t a) {
    float2 v;
    asm volatile("ld.shared.v2.f32 {%0, %1}, [%2];" : "=f"(v.x), "=f"(v.y) : "r"(a));
    return v;
}
__device__ __forceinline__ void ldsm4(unsigned* r, uint32_t a) {
    asm volatile("ldmatrix.sync.aligned.m8n8.x4.shared.b16 {%0, %1, %2, %3}, [%4];"
                 : "=r"(r[0]), "=r"(r[1]), "=r"(r[2]), "=r"(r[3]) : "r"(a));
}
__device__ __forceinline__ void mma16(float* d, const unsigned* a, unsigned b0, unsigned b1) {
    asm volatile(
        "mma.sync.aligned.m16n8k16.row.col.f32.f16.f16.f32 "
        "{%0,%1,%2,%3}, {%4,%5,%6,%7}, {%8,%9}, {%0,%1,%2,%3};"
        : "+f"(d[0]), "+f"(d[1]), "+f"(d[2]), "+f"(d[3])
        : "r"(a[0]), "r"(a[1]), "r"(a[2]), "r"(a[3]), "r"(b0), "r"(b1));
}
__device__ __forceinline__ unsigned packh2(float x, float y) {
    __half2 t = __floats2half2_rn(x, y);
    return *reinterpret_cast<unsigned*>(&t);
}
__device__ __forceinline__ float2 unpackh2(unsigned u) {
    __half2 t = *reinterpret_cast<__half2*>(&u);
    return __half22float2(t);
}

// ---------------------------------------------------------------------------
// 0) Weight repack to lds128 fragment layout.
// ---------------------------------------------------------------------------
__global__ void repack_w_kernel(const float* __restrict__ Wq,
                                const float* __restrict__ Wk,
                                const float* __restrict__ Wv) {
    int idx = blockIdx.x * 256 + threadIdx.x;
    if (idx >= 54 * 2048) return;
    int mi = idx >> 11, e = idx & 2047;
    int cg = e >> 9, ks = (e >> 7) & 3, lane = (e >> 2) & 31, u = e & 3;
    int cin  = 16 * ks + 2 * (lane & 3) + 8 * (u & 1);
    int cout = 16 * cg + 8 * (u >> 1) + (lane >> 2);
    int s0 = mi * 4096 + cin * 64 + cout;
    g_wkv_ph[mi * 4096 + e]        = packh2(Wk[s0], Wk[s0 + 64]);
    g_wkv_ph[mi * 4096 + 2048 + e] = packh2(Wv[s0], Wv[s0 + 64]);
    if (mi < 2)
        g_wq_ph[mi * 2048 + e] = packh2(Wq[s0], Wq[s0 + 64]);
}

// ---------------------------------------------------------------------------
// 1a) BatchNorm partial sums: 64 CTAs x 256 threads
// ---------------------------------------------------------------------------
__global__ void bn_part_kernel(const float* __restrict__ x) {
    float s0 = 0.f, s1 = 0.f, s2 = 0.f, t0 = 0.f, t1 = 0.f, t2 = 0.f;
    int base = blockIdx.x * 512;
    for (int i = threadIdx.x; i < 512; i += 256) {
        int p = base + i;
        float v0 = x[p * 3 + 0], v1 = x[p * 3 + 1], v2 = x[p * 3 + 2];
        s0 += v0; s1 += v1; s2 += v2;
        t0 += v0 * v0; t1 += v1 * v1; t2 += v2 * v2;
    }
#pragma unroll
    for (int o = 16; o; o >>= 1) {
        s0 += __shfl_xor_sync(0xffffffffu, s0, o);
        s1 += __shfl_xor_sync(0xffffffffu, s1, o);
        s2 += __shfl_xor_sync(0xffffffffu, s2, o);
        t0 += __shfl_xor_sync(0xffffffffu, t0, o);
        t1 += __shfl_xor_sync(0xffffffffu, t1, o);
        t2 += __shfl_xor_sync(0xffffffffu, t2, o);
    }
    __shared__ float red[8][6];
    int lane = threadIdx.x & 31, w = threadIdx.x >> 5;
    if (lane == 0) {
        red[w][0] = s0; red[w][1] = s1; red[w][2] = s2;
        red[w][3] = t0; red[w][4] = t1; red[w][5] = t2;
    }
    __syncthreads();
    if (threadIdx.x < 6) {
        float a = 0.f;
#pragma unroll
        for (int r = 0; r < 8; r++) a += red[r][threadIdx.x];
        g_part[blockIdx.x * 6 + threadIdx.x] = a;
    }
}

// ---------------------------------------------------------------------------
// 1b) BN finalize: 1 CTA, 32 threads
// ---------------------------------------------------------------------------
__global__ void bn_fin_kernel() {
    int lane = threadIdx.x;
    float a[6];
#pragma unroll
    for (int k = 0; k < 6; k++)
        a[k] = g_part[lane * 6 + k] + g_part[(lane + 32) * 6 + k];
#pragma unroll
    for (int o = 16; o; o >>= 1)
#pragma unroll
        for (int k = 0; k < 6; k++)
            a[k] += __shfl_xor_sync(0xffffffffu, a[k], o);
    if (lane == 0) {
        const float inv = 1.0f / (float)NQ;
        float m0 = a[0] * inv, m1 = a[1] * inv, m2 = a[2] * inv;
        g_stats[0] = m0; g_stats[1] = m1; g_stats[2] = m2;
        g_stats[4] = rsqrtf(a[3] * inv - m0 * m0 + 1e-5f);
        g_stats[5] = rsqrtf(a[4] * inv - m1 * m1 + 1e-5f);
        g_stats[6] = rsqrtf(a[5] * inv - m2 * m2 + 1e-5f);
    }
}

// ---------------------------------------------------------------------------
// 2) h0 = normalize(x) @ W_in + b_in
// ---------------------------------------------------------------------------
__global__ void input_proj_kernel(const float* __restrict__ x,
                                  const float* __restrict__ W_in,
                                  const float* __restrict__ b_in,
                                  float* __restrict__ h_out,
                                  __half* __restrict__ hf_out) {
    int idx = blockIdx.x * 256 + threadIdx.x;
    int p = idx >> 6, c = idx & 63;
    float acc = b_in[c];
#pragma unroll
    for (int f = 0; f < 3; f++) {
        float xn = (x[p * 3 + f] - g_stats[f]) * g_stats[4 + f];
        acc += xn * W_in[f * 64 + c];
    }
    h_out[idx] = acc;
    hf_out[idx] = __float2half_rn(acc);
}

// ---------------------------------------------------------------------------
// staging
// ---------------------------------------------------------------------------
__device__ __forceinline__ void stage_region(uint32_t sb, const __half* hf,
                                             int pos_rb, int tid) {
    for (int u = tid; u < 1560; u += 256) {
        int r = u >> 3, c4 = u & 7;
        uint32_t dst = sb + (r << 7) + ((c4 ^ (r & 7)) << 4);
        int pos = pos_rb + r;
        int ok = (unsigned)pos < (unsigned)NQ;
        cpa16z(dst, hf + (size_t)(ok ? pos : 0) * 64 + c4 * 8, ok);
    }
}
__device__ __forceinline__ void stage_B(uint32_t dst, const unsigned* w, int tid) {
#pragma unroll
    for (int i = 0; i < 4; i++) {
        int u = tid + (i << 8);
        cpa16(dst + (u << 4), w + (u << 2));
    }
}

// ---------------------------------------------------------------------------
// 3) Fused attention (R11 structure; biases folded into mma accumulator init)
// ---------------------------------------------------------------------------
__global__ __launch_bounds__(256, 2)
void attn_kernel(const float* __restrict__ h_in, const __half* __restrict__ hf,
                 float* __restrict__ h_out, __half* __restrict__ hfo,
                 const unsigned* __restrict__ wq_ph, const float* __restrict__ bq,
                 const unsigned* __restrict__ wkv_ph,
                 const float* __restrict__ bk, const float* __restrict__ bv) {
    extern __shared__ char smem[];
    const uint32_t sb = smem_u32(smem);
    const int tid  = threadIdx.x;
    const int lane = tid & 31;
    const int w    = tid >> 5;
    const int tig  = lane & 3;
    const int l4   = lane >> 2;
    const int rg   = w & 1;
    const int cg   = w >> 1;
    const int lrow = lane & 15;
    const int lhi  = lane >> 4;

    const int bx    = blockIdx.x;
    const int tbase = bx << 7;
    const int a0    = (bx & 7) << 2;
    const uint32_t bKoff = (uint32_t)(cg << 11) + (uint32_t)(lane << 4);
    const uint32_t biasOff = (uint32_t)((cg << 6) + (tig << 3));

    // ---- prologue: region(dt=0), Wq -> BB1, B[m=9] -> BB0, biases ----
    stage_region(sb, hf, tbase - 33, tid);
    for (int u = tid; u < 512; u += 256)
        cpa16(sb + BB1 + (u << 4), wq_ph + (u << 2));
    stage_B(sb + BB0, wkv_ph + 9 * 4096, tid);
    for (int u = tid; u < 880; u += 256) {
        if (u < 432)      cpa16(sb + BIASK + (u << 4), bk + (u << 2));
        else if (u < 864) cpa16(sb + BIASV + ((u - 432) << 4), bv + ((u - 432) << 2));
        else              cpa16(sb + BIASQ + ((u - 864) << 4), bq + ((u - 864) << 2));
    }
    CPA_COMMIT(); CPA_WAIT0();
    __syncthreads();

    // ---- Q projection (bias folded into accumulator init) ----
    unsigned qp[16];
    {
        int rl = 33 + (rg << 6) + lrow;
        uint32_t abase = sb + (rl << 7);
        int xs = rl & 7;
        float2 bq0 = lds64f(sb + BIASQ + biasOff);
        float2 bq1 = lds64f(sb + BIASQ + biasOff + 32);
        float qf[32];
#pragma unroll
        for (int mt = 0; mt < 4; mt++)
#pragma unroll
            for (int j = 0; j < 2; j++) {
                float2 b2 = j ? bq1 : bq0;
                qf[(mt * 2 + j) * 4 + 0] = b2.x;
                qf[(mt * 2 + j) * 4 + 1] = b2.y;
                qf[(mt * 2 + j) * 4 + 2] = b2.x;
                qf[(mt * 2 + j) * 4 + 3] = b2.y;
            }
#pragma unroll
        for (int ks = 0; ks < 4; ks++) {
            unsigned bf[4];
            lds128u(bf, sb + BB1 + bKoff + (ks << 9));
#pragma unroll
            for (int mt = 0; mt < 4; mt++) {
                unsigned a[4];
                ldsm4(a, abase + (mt << 11) + ((unsigned)(((2 * ks + lhi) ^ xs)) << 4));
                mma16(&qf[(mt * 2 + 0) * 4], a, bf[0], bf[1]);
                mma16(&qf[(mt * 2 + 1) * 4], a, bf[2], bf[3]);
            }
        }
#pragma unroll
        for (int mt = 0; mt < 4; mt++)
#pragma unroll
            for (int j = 0; j < 2; j++)
#pragma unroll
                for (int rh = 0; rh < 2; rh++)
                    qp[(mt * 2 + j) * 2 + rh] =
                        packh2(qf[(mt * 2 + j) * 4 + rh * 2 + 0],
                               qf[(mt * 2 + j) * 4 + rh * 2 + 1]);
    }

    // ---- spatial validity masks ----
    unsigned vm[8];
#pragma unroll
    for (int t = 0; t < 8; t++) {
        int lr = (rg << 6) + l4 + ((t >> 1) << 4) + ((t & 1) << 3);
        int ga = a0 + (lr >> 5), gb = lr & 31;
        bool aM = (ga > 0), aP = (ga < 31), bM = (gb > 0), bP = (gb < 31);
        unsigned v = 0;
#pragma unroll
        for (int m = 0; m < MOFF; m++) {
            int r9 = m % 9;
            int di = r9 / 3 - 1, dj = r9 % 3 - 1;
            bool ok = (di < 0 ? aM : (di > 0 ? aP : true)) &&
                      (dj < 0 ? bM : (dj > 0 ? bP : true));
            v |= ((unsigned)ok) << m;
        }
        vm[t] = v;
    }

    float acc[32], den[8];
#pragma unroll
    for (int e = 0; e < 32; e++) acc[e] = 0.0f;
#pragma unroll
    for (int t = 0; t < 8; t++) den[t] = 0.0f;

    // ---- 27-offset mainloop (dt-grouped: 9..17, 0..8, 18..26) ----
#pragma unroll 1
    for (int i = 0; i < MOFF; i++) {
        int m = i + (i < 9 ? 9 : (i < 18 ? -9 : 0));
        CPA_WAIT0();
        __syncthreads();
        if (i < 26) {
            int mn = i + 1;
            mn += (mn < 9 ? 9 : (mn < 18 ? -9 : 0));
            stage_B(sb + ((i & 1) ? BB0 : BB1), wkv_ph + mn * 4096, tid);
            CPA_COMMIT();
        }
        const uint32_t bB = sb + ((i & 1) ? BB1 : BB0);
        int r9 = m % 9;
        int di = r9 / 3 - 1, dj = r9 % 3 - 1;

        // biases for this offset — consumed as accumulator init (pre-sweep)
        float2 bk2[2], bv2[2];
        bk2[0] = lds64f(sb + BIASK + (m << 8) + biasOff);
        bk2[1] = lds64f(sb + BIASK + (m << 8) + biasOff + 32);
        bv2[0] = lds64f(sb + BIASV + (m << 8) + biasOff);
        bv2[1] = lds64f(sb + BIASV + (m << 8) + biasOff + 32);

        int rl = 33 + di * 32 + dj + (rg << 6) + lrow;
        uint32_t abase = sb + (rl << 7);
        int xs = rl & 7;

#pragma unroll
        for (int hf2 = 0; hf2 < 2; hf2++) {
            float dK[16], dV[16];
#pragma unroll
            for (int mtl = 0; mtl < 2; mtl++)
#pragma unroll
                for (int j = 0; j < 2; j++) {
                    dK[mtl * 8 + j * 4 + 0] = bk2[j].x;
                    dK[mtl * 8 + j * 4 + 1] = bk2[j].y;
                    dK[mtl * 8 + j * 4 + 2] = bk2[j].x;
                    dK[mtl * 8 + j * 4 + 3] = bk2[j].y;
                    dV[mtl * 8 + j * 4 + 0] = bv2[j].x;
                    dV[mtl * 8 + j * 4 + 1] = bv2[j].y;
                    dV[mtl * 8 + j * 4 + 2] = bv2[j].x;
                    dV[mtl * 8 + j * 4 + 3] = bv2[j].y;
                }
#pragma unroll
            for (int ks = 0; ks < 4; ks++) {
                unsigned bkf[4], bvf[4];
                lds128u(bkf, bB + bKoff + (ks << 9));
                lds128u(bvf, bB + 8192u + bKoff + (ks << 9));
#pragma unroll
                for (int mtl = 0; mtl < 2; mtl++) {
                    int mt = hf2 * 2 + mtl;
                    unsigned a[4];
                    ldsm4(a, abase + (mt << 11) +
                              ((unsigned)(((2 * ks + lhi) ^ xs)) << 4));
                    mma16(&dK[mtl * 8 + 0], a, bkf[0], bkf[1]);
                    mma16(&dK[mtl * 8 + 4], a, bkf[2], bkf[3]);
                    mma16(&dV[mtl * 8 + 0], a, bvf[0], bvf[1]);
                    mma16(&dV[mtl * 8 + 4], a, bvf[2], bvf[3]);
                }
            }
            float sp[4];
#pragma unroll
            for (int t = 0; t < 4; t++) sp[t] = 0.0f;
#pragma unroll
            for (int mtl = 0; mtl < 2; mtl++)
#pragma unroll
                for (int j = 0; j < 2; j++) {
                    int mt = hf2 * 2 + mtl;
#pragma unroll
                    for (int rh = 0; rh < 2; rh++) {
                        float2 qv = unpackh2(qp[(mt * 2 + j) * 2 + rh]);
                        sp[mtl * 2 + rh] +=
                            dK[mtl * 8 + j * 4 + rh * 2 + 0] * qv.x +
                            dK[mtl * 8 + j * 4 + rh * 2 + 1] * qv.y;
                    }
                }
            float p[4];
#pragma unroll
            for (int t = 0; t < 4; t++) {
                float s = sp[t];
                s += __shfl_xor_sync(0xffffffffu, s, 1);
                s += __shfl_xor_sync(0xffffffffu, s, 2);
                int gt = hf2 * 4 + ((t >> 1) << 1) + (t & 1);
                bool ok = (vm[gt] >> m) & 1u;
                float pv = __expf(ok ? s : -1e30f);
                p[t] = pv;
                den[gt] += pv;
            }
#pragma unroll
            for (int mtl = 0; mtl < 2; mtl++)
#pragma unroll
                for (int j = 0; j < 2; j++) {
                    int mt = hf2 * 2 + mtl;
#pragma unroll
                    for (int rh = 0; rh < 2; rh++) {
                        float pw = p[mtl * 2 + rh];
                        acc[(mt * 2 + j) * 4 + rh * 2 + 0] +=
                            pw * dV[mtl * 8 + j * 4 + rh * 2 + 0];
                        acc[(mt * 2 + j) * 4 + rh * 2 + 1] +=
                            pw * dV[mtl * 8 + j * 4 + rh * 2 + 1];
                    }
                }
        }

        if (i == 8 || i == 17) {
            __syncthreads();
            int dt = (i == 8) ? -1 : 1;
            stage_region(sb, hf, tbase + dt * 1024 - 33, tid);
            CPA_COMMIT();
        }
    }

    // ---- epilogue ----
#pragma unroll
    for (int mt = 0; mt < 4; mt++)
#pragma unroll
        for (int rh = 0; rh < 2; rh++) {
            int pos = tbase + (rg << 6) + l4 + (mt << 4) + (rh << 3);
            float iv = 1.0f / den[mt * 2 + rh];
            const float* rp = h_in + ((size_t)pos << 6);
            float* op = h_out + ((size_t)pos << 6);
#pragma unroll
            for (int j = 0; j < 2; j++) {
                int c = 16 * cg + 8 * j + 2 * tig;
                float2 r = *(const float2*)(rp + c);
                float ox = acc[(mt * 2 + j) * 4 + rh * 2 + 0] * iv + r.x;
                float oy = acc[(mt * 2 + j) * 4 + rh * 2 + 1] * iv + r.y;
                float2 o; o.x = ox; o.y = oy;
                *(float2*)(op + c) = o;
                if (hfo) {
                    __half2 h2 = __floats2half2_rn(ox, oy);
                    *(unsigned*)(&hfo[(size_t)pos * 64 + c]) = *(unsigned*)&h2;
                }
            }
        }
}

// ---------------------------------------------------------------------------
// 4) out = h @ W_out + b_out
// ---------------------------------------------------------------------------
__global__ void out_proj_kernel(const float* __restrict__ h,
                                const float* __restrict__ W_out,
                                const float* __restrict__ b_out,
                                float* __restrict__ out) {
    __shared__ float hs[32 * 64];
    int tid = threadIdx.x;
    int base = blockIdx.x * 32;
    for (int j = tid; j < 2048; j += 128) hs[j] = h[base * 64 + j];
    __syncthreads();
    if (tid < 96) {
        int rr = tid / 3, f = tid - 3 * (tid / 3);
        float acc = b_out[f];
#pragma unroll 8
        for (int cp = 0; cp < 64; cp++)
            acc += hs[rr * 64 + cp] * W_out[cp * 3 + f];
        out[(base + rr) * 3 + f] = acc;
    }
}

// ---------------------------------------------------------------------------
extern "C" void kernel_launch(void* const* d_in, const int* in_sizes, int n_in,
                              void* d_out, int out_size) {
    const float* x     = (const float*)d_in[0];
    const float* W_in  = (const float*)d_in[1];
    const float* b_in  = (const float*)d_in[2];
    const float* W_out = (const float*)d_in[3];
    const float* b_out = (const float*)d_in[4];
    const float* Wq    = (const float*)d_in[5];
    const float* bq    = (const float*)d_in[6];
    const float* Wk    = (const float*)d_in[7];
    const float* bk    = (const float*)d_in[8];
    const float* Wv    = (const float*)d_in[9];
    const float* bv    = (const float*)d_in[10];
    float* out = (float*)d_out;

    float *h0, *h1;
    __half *hf0, *hf1;
    unsigned *wq_ph, *wkv_ph;
    cudaGetSymbolAddress((void**)&h0, g_h0);
    cudaGetSymbolAddress((void**)&h1, g_h1);
    cudaGetSymbolAddress((void**)&hf0, g_hf0);
    cudaGetSymbolAddress((void**)&hf1, g_hf1);
    cudaGetSymbolAddress((void**)&wq_ph, g_wq_ph);
    cudaGetSymbolAddress((void**)&wkv_ph, g_wkv_ph);
    cudaFuncSetAttribute(attn_kernel, cudaFuncAttributeMaxDynamicSharedMemorySize, SMEMB);

    repack_w_kernel<<<(54 * 2048 + 255) / 256, 256>>>(Wq, Wk, Wv);
    bn_part_kernel<<<64, 256>>>(x);
    bn_fin_kernel<<<1, 32>>>();
    input_proj_kernel<<<(NQ * 64) / 256, 256>>>(x, W_in, b_in, h0, hf0);

    attn_kernel<<<256, 256, SMEMB>>>(h0, hf0, h1, hf1,
        wq_ph, bq, wkv_ph, bk, bv);
    attn_kernel<<<256, 256, SMEMB>>>(h1, hf1, h0, (__half*)nullptr,
        wq_ph + 2048, bq + 64, wkv_ph + 27 * 4096, bk + 27 * 64, bv + 27 * 64);

    out_proj_kernel<<<NQ / 32, 128>>>(h0, W_out, b_out, out);
}

// round 17
// speedup vs baseline: 1.2250x; 1.0698x over previous
#include <cuda_runtime.h>
#include <cuda_fp16.h>
#include <math.h>
#include <stdint.h>

#define NQ   32768
#define MOFF 27

// smem: A region (195 rows x 128B fp16) + 2 B buffers (16KB) + biases
#define ARH    0
#define BB0    24960
#define BB1    41344
#define BIASK  57728     // 27*64 fp32 = 6912B
#define BIASV  64640
#define BIASQ  71552
#define SMEMB  71808

// Scratch (static device globals: allocation-free per harness rules)
__device__ float g_h0[NQ * 64];
__device__ float g_h1[NQ * 64];
__device__ __half g_hf0[NQ * 64];
__device__ __half g_hf1[NQ * 64];
__device__ float g_stats[8];
__device__ float g_part[64 * 6];
__device__ unsigned g_wq_ph[2 * 2048];
__device__ unsigned g_wkv_ph[54 * 4096];

// ---------------------------------------------------------------------------
__device__ __forceinline__ uint32_t smem_u32(const void* p) {
    uint32_t a;
    asm("{ .reg .u64 t; cvta.to.shared.u64 t, %1; cvt.u32.u64 %0, t; }" : "=r"(a) : "l"(p));
    return a;
}
__device__ __forceinline__ void cpa16z(uint32_t dst, const void* src, int ok) {
    asm volatile("cp.async.cg.shared.global [%0], [%1], 16, %2;"
                 :: "r"(dst), "l"(src), "r"(ok ? 16 : 0));
}
__device__ __forceinline__ void cpa16(uint32_t dst, const void* src) {
    asm volatile("cp.async.cg.shared.global [%0], [%1], 16;" :: "r"(dst), "l"(src));
}
#define CPA_COMMIT() asm volatile("cp.async.commit_group;" ::: "memory")
#define CPA_WAIT0()  asm volatile("cp.async.wait_group 0;"  ::: "memory")

__device__ __forceinline__ void lds128u(unsigned* v, uint32_t a) {
    asm volatile("ld.shared.v4.b32 {%0, %1, %2, %3}, [%4];"
                 : "=r"(v[0]), "=r"(v[1]), "=r"(v[2]), "=r"(v[3]) : "r"(a));
}
__device__ __forceinline__ float2 lds64f(uint32_t a) {
    float2 v;
    asm volatile("ld.shared.v2.f32 {%0, %1}, [%2];" : "=f"(v.x), "=f"(v.y) : "r"(a));
    return v;
}
__device__ __forceinline__ void ldsm4(unsigned* r, uint32_t a) {
    asm volatile("ldmatrix.sync.aligned.m8n8.x4.shared.b16 {%0, %1, %2, %3}, [%4];"
                 : "=r"(r[0]), "=r"(r[1]), "=r"(r[2]), "=r"(r[3]) : "r"(a));
}
__device__ __forceinline__ void mma16(float* d, const unsigned* a, unsigned b0, unsigned b1) {
    asm volatile(
        "mma.sync.aligned.m16n8k16.row.col.f32.f16.f16.f32 "
        "{%0,%1,%2,%3}, {%4,%5,%6,%7}, {%8,%9}, {%0,%1,%2,%3};"
        : "+f"(d[0]), "+f"(d[1]), "+f"(d[2]), "+f"(d[3])
        : "r"(a[0]), "r"(a[1]), "r"(a[2]), "r"(a[3]), "r"(b0), "r"(b1));
}
__device__ __forceinline__ unsigned packh2(float x, float y) {
    __half2 t = __floats2half2_rn(x, y);
    return *reinterpret_cast<unsigned*>(&t);
}
__device__ __forceinline__ float2 unpackh2(unsigned u) {
    __half2 t = *reinterpret_cast<__half2*>(&u);
    return __half22float2(t);
}

// ---------------------------------------------------------------------------
// 0) Prep kernel: blocks [0,432) repack weights; blocks [432,496) BN partials
// ---------------------------------------------------------------------------
__global__ void prep_kernel(const float* __restrict__ Wq,
                            const float* __restrict__ Wk,
                            const float* __restrict__ Wv,
                            const float* __restrict__ x) {
    if (blockIdx.x < 432) {
        int idx = blockIdx.x * 256 + threadIdx.x;
        if (idx >= 54 * 2048) return;
        int mi = idx >> 11, e = idx & 2047;
        int cg = e >> 9, ks = (e >> 7) & 3, lane = (e >> 2) & 31, u = e & 3;
        int cin  = 16 * ks + 2 * (lane & 3) + 8 * (u & 1);
        int cout = 16 * cg + 8 * (u >> 1) + (lane >> 2);
        int s0 = mi * 4096 + cin * 64 + cout;
        g_wkv_ph[mi * 4096 + e]        = packh2(Wk[s0], Wk[s0 + 64]);
        g_wkv_ph[mi * 4096 + 2048 + e] = packh2(Wv[s0], Wv[s0 + 64]);
        if (mi < 2)
            g_wq_ph[mi * 2048 + e] = packh2(Wq[s0], Wq[s0 + 64]);
        return;
    }
    // BN partial sums over 512 positions per block
    int bb = blockIdx.x - 432;
    float s0 = 0.f, s1 = 0.f, s2 = 0.f, t0 = 0.f, t1 = 0.f, t2 = 0.f;
    int base = bb * 512;
    for (int i = threadIdx.x; i < 512; i += 256) {
        int p = base + i;
        float v0 = x[p * 3 + 0], v1 = x[p * 3 + 1], v2 = x[p * 3 + 2];
        s0 += v0; s1 += v1; s2 += v2;
        t0 += v0 * v0; t1 += v1 * v1; t2 += v2 * v2;
    }
#pragma unroll
    for (int o = 16; o; o >>= 1) {
        s0 += __shfl_xor_sync(0xffffffffu, s0, o);
        s1 += __shfl_xor_sync(0xffffffffu, s1, o);
        s2 += __shfl_xor_sync(0xffffffffu, s2, o);
        t0 += __shfl_xor_sync(0xffffffffu, t0, o);
        t1 += __shfl_xor_sync(0xffffffffu, t1, o);
        t2 += __shfl_xor_sync(0xffffffffu, t2, o);
    }
    __shared__ float red[8][6];
    int lane = threadIdx.x & 31, w = threadIdx.x >> 5;
    if (lane == 0) {
        red[w][0] = s0; red[w][1] = s1; red[w][2] = s2;
        red[w][3] = t0; red[w][4] = t1; red[w][5] = t2;
    }
    __syncthreads();
    if (threadIdx.x < 6) {
        float a = 0.f;
#pragma unroll
        for (int r = 0; r < 8; r++) a += red[r][threadIdx.x];
        g_part[bb * 6 + threadIdx.x] = a;
    }
}

// ---------------------------------------------------------------------------
// 1) BN finalize: 1 CTA, 32 threads
// ---------------------------------------------------------------------------
__global__ void bn_fin_kernel() {
    int lane = threadIdx.x;
    float a[6];
#pragma unroll
    for (int k = 0; k < 6; k++)
        a[k] = g_part[lane * 6 + k] + g_part[(lane + 32) * 6 + k];
#pragma unroll
    for (int o = 16; o; o >>= 1)
#pragma unroll
        for (int k = 0; k < 6; k++)
            a[k] += __shfl_xor_sync(0xffffffffu, a[k], o);
    if (lane == 0) {
        const float inv = 1.0f / (float)NQ;
        float m0 = a[0] * inv, m1 = a[1] * inv, m2 = a[2] * inv;
        g_stats[0] = m0; g_stats[1] = m1; g_stats[2] = m2;
        g_stats[4] = rsqrtf(a[3] * inv - m0 * m0 + 1e-5f);
        g_stats[5] = rsqrtf(a[4] * inv - m1 * m1 + 1e-5f);
        g_stats[6] = rsqrtf(a[5] * inv - m2 * m2 + 1e-5f);
    }
}

// ---------------------------------------------------------------------------
// 2) h0 = normalize(x) @ W_in + b_in   (vectorized: thread = 4 channels)
// ---------------------------------------------------------------------------
__global__ void input_proj_kernel(const float* __restrict__ x,
                                  const float* __restrict__ W_in,
                                  const float* __restrict__ b_in,
                                  float* __restrict__ h_out,
                                  __half* __restrict__ hf_out) {
    int idx = blockIdx.x * 256 + threadIdx.x;       // NQ*16 threads
    int p = idx >> 4, c4 = (idx & 15) << 2;
    float4 acc = *(const float4*)(b_in + c4);
    float xn0 = (x[p * 3 + 0] - g_stats[0]) * g_stats[4];
    float xn1 = (x[p * 3 + 1] - g_stats[1]) * g_stats[5];
    float xn2 = (x[p * 3 + 2] - g_stats[2]) * g_stats[6];
    float4 w0 = *(const float4*)(W_in + c4);
    float4 w1 = *(const float4*)(W_in + 64 + c4);
    float4 w2 = *(const float4*)(W_in + 128 + c4);
    acc.x += xn0 * w0.x + xn1 * w1.x + xn2 * w2.x;
    acc.y += xn0 * w0.y + xn1 * w1.y + xn2 * w2.y;
    acc.z += xn0 * w0.z + xn1 * w1.z + xn2 * w2.z;
    acc.w += xn0 * w0.w + xn1 * w1.w + xn2 * w2.w;
    *(float4*)(h_out + (size_t)p * 64 + c4) = acc;
    uint2 hh;
    hh.x = packh2(acc.x, acc.y);
    hh.y = packh2(acc.z, acc.w);
    *(uint2*)(hf_out + (size_t)p * 64 + c4) = hh;
}

// ---------------------------------------------------------------------------
// staging
// ---------------------------------------------------------------------------
__device__ __forceinline__ void stage_region(uint32_t sb, const __half* hf,
                                             int pos_rb, int tid) {
    for (int u = tid; u < 1560; u += 256) {
        int r = u >> 3, c4 = u & 7;
        uint32_t dst = sb + (r << 7) + ((c4 ^ (r & 7)) << 4);
        int pos = pos_rb + r;
        int ok = (unsigned)pos < (unsigned)NQ;
        cpa16z(dst, hf + (size_t)(ok ? pos : 0) * 64 + c4 * 8, ok);
    }
}
__device__ __forceinline__ void stage_B(uint32_t dst, const unsigned* w, int tid) {
#pragma unroll
    for (int i = 0; i < 4; i++) {
        int u = tid + (i << 8);
        cpa16(dst + (u << 4), w + (u << 2));
    }
}

// ---------------------------------------------------------------------------
// 3) Fused attention (R11 configuration — best measured)
// ---------------------------------------------------------------------------
__global__ __launch_bounds__(256, 2)
void attn_kernel(const float* __restrict__ h_in, const __half* __restrict__ hf,
                 float* __restrict__ h_out, __half* __restrict__ hfo,
                 const unsigned* __restrict__ wq_ph, const float* __restrict__ bq,
                 const unsigned* __restrict__ wkv_ph,
                 const float* __restrict__ bk, const float* __restrict__ bv) {
    extern __shared__ char smem[];
    const uint32_t sb = smem_u32(smem);
    const int tid  = threadIdx.x;
    const int lane = tid & 31;
    const int w    = tid >> 5;
    const int tig  = lane & 3;
    const int l4   = lane >> 2;
    const int rg   = w & 1;
    const int cg   = w >> 1;
    const int lrow = lane & 15;
    const int lhi  = lane >> 4;

    const int bx    = blockIdx.x;
    const int tbase = bx << 7;
    const int a0    = (bx & 7) << 2;
    const uint32_t bKoff = (uint32_t)(cg << 11) + (uint32_t)(lane << 4);
    const uint32_t biasOff = (uint32_t)((cg << 6) + (tig << 3));

    // ---- prologue: region(dt=0), Wq -> BB1, B[m=9] -> BB0, biases ----
    stage_region(sb, hf, tbase - 33, tid);
    for (int u = tid; u < 512; u += 256)
        cpa16(sb + BB1 + (u << 4), wq_ph + (u << 2));
    stage_B(sb + BB0, wkv_ph + 9 * 4096, tid);
    for (int u = tid; u < 880; u += 256) {
        if (u < 432)      cpa16(sb + BIASK + (u << 4), bk + (u << 2));
        else if (u < 864) cpa16(sb + BIASV + ((u - 432) << 4), bv + ((u - 432) << 2));
        else              cpa16(sb + BIASQ + ((u - 864) << 4), bq + ((u - 864) << 2));
    }
    CPA_COMMIT(); CPA_WAIT0();
    __syncthreads();

    // ---- Q projection ----
    unsigned qp[16];
    {
        int rl = 33 + (rg << 6) + lrow;
        uint32_t abase = sb + (rl << 7);
        int xs = rl & 7;
        float qf[32];
#pragma unroll
        for (int e = 0; e < 32; e++) qf[e] = 0.0f;
#pragma unroll
        for (int ks = 0; ks < 4; ks++) {
            unsigned bf[4];
            lds128u(bf, sb + BB1 + bKoff + (ks << 9));
#pragma unroll
            for (int mt = 0; mt < 4; mt++) {
                unsigned a[4];
                ldsm4(a, abase + (mt << 11) + ((unsigned)(((2 * ks + lhi) ^ xs)) << 4));
                mma16(&qf[(mt * 2 + 0) * 4], a, bf[0], bf[1]);
                mma16(&qf[(mt * 2 + 1) * 4], a, bf[2], bf[3]);
            }
        }
        float2 bq0 = lds64f(sb + BIASQ + biasOff);
        float2 bq1 = lds64f(sb + BIASQ + biasOff + 32);
#pragma unroll
        for (int mt = 0; mt < 4; mt++)
#pragma unroll
            for (int j = 0; j < 2; j++) {
                float2 b2 = j ? bq1 : bq0;
#pragma unroll
                for (int rh = 0; rh < 2; rh++)
                    qp[(mt * 2 + j) * 2 + rh] =
                        packh2(qf[(mt * 2 + j) * 4 + rh * 2 + 0] + b2.x,
                               qf[(mt * 2 + j) * 4 + rh * 2 + 1] + b2.y);
            }
    }

    // ---- spatial validity masks ----
    unsigned vm[8];
#pragma unroll
    for (int t = 0; t < 8; t++) {
        int lr = (rg << 6) + l4 + ((t >> 1) << 4) + ((t & 1) << 3);
        int ga = a0 + (lr >> 5), gb = lr & 31;
        bool aM = (ga > 0), aP = (ga < 31), bM = (gb > 0), bP = (gb < 31);
        unsigned v = 0;
#pragma unroll
        for (int m = 0; m < MOFF; m++) {
            int r9 = m % 9;
            int di = r9 / 3 - 1, dj = r9 % 3 - 1;
            bool ok = (di < 0 ? aM : (di > 0 ? aP : true)) &&
                      (dj < 0 ? bM : (dj > 0 ? bP : true));
            v |= ((unsigned)ok) << m;
        }
        vm[t] = v;
    }

    float acc[32], den[8];
#pragma unroll
    for (int e = 0; e < 32; e++) acc[e] = 0.0f;
#pragma unroll
    for (int t = 0; t < 8; t++) den[t] = 0.0f;

    // ---- 27-offset mainloop (dt-grouped: 9..17, 0..8, 18..26) ----
#pragma unroll 1
    for (int i = 0; i < MOFF; i++) {
        int m = i + (i < 9 ? 9 : (i < 18 ? -9 : 0));
        CPA_WAIT0();
        __syncthreads();
        if (i < 26) {
            int mn = i + 1;
            mn += (mn < 9 ? 9 : (mn < 18 ? -9 : 0));
            stage_B(sb + ((i & 1) ? BB0 : BB1), wkv_ph + mn * 4096, tid);
            CPA_COMMIT();
        }
        const uint32_t bB = sb + ((i & 1) ? BB1 : BB0);
        int r9 = m % 9;
        int di = r9 / 3 - 1, dj = r9 % 3 - 1;

        float2 bk2[2], bv2[2];
        bk2[0] = lds64f(sb + BIASK + (m << 8) + biasOff);
        bk2[1] = lds64f(sb + BIASK + (m << 8) + biasOff + 32);
        bv2[0] = lds64f(sb + BIASV + (m << 8) + biasOff);
        bv2[1] = lds64f(sb + BIASV + (m << 8) + biasOff + 32);

        int rl = 33 + di * 32 + dj + (rg << 6) + lrow;
        uint32_t abase = sb + (rl << 7);
        int xs = rl & 7;

#pragma unroll
        for (int hf2 = 0; hf2 < 2; hf2++) {
            float dK[16], dV[16];
#pragma unroll
            for (int e = 0; e < 16; e++) { dK[e] = 0.0f; dV[e] = 0.0f; }
#pragma unroll
            for (int ks = 0; ks < 4; ks++) {
                unsigned bkf[4], bvf[4];
                lds128u(bkf, bB + bKoff + (ks << 9));
                lds128u(bvf, bB + 8192u + bKoff + (ks << 9));
#pragma unroll
                for (int mtl = 0; mtl < 2; mtl++) {
                    int mt = hf2 * 2 + mtl;
                    unsigned a[4];
                    ldsm4(a, abase + (mt << 11) +
                              ((unsigned)(((2 * ks + lhi) ^ xs)) << 4));
                    mma16(&dK[mtl * 8 + 0], a, bkf[0], bkf[1]);
                    mma16(&dK[mtl * 8 + 4], a, bkf[2], bkf[3]);
                    mma16(&dV[mtl * 8 + 0], a, bvf[0], bvf[1]);
                    mma16(&dV[mtl * 8 + 4], a, bvf[2], bvf[3]);
                }
            }
            float sp[4];
#pragma unroll
            for (int t = 0; t < 4; t++) sp[t] = 0.0f;
#pragma unroll
            for (int mtl = 0; mtl < 2; mtl++)
#pragma unroll
                for (int j = 0; j < 2; j++) {
                    int mt = hf2 * 2 + mtl;
#pragma unroll
                    for (int rh = 0; rh < 2; rh++) {
                        float2 qv = unpackh2(qp[(mt * 2 + j) * 2 + rh]);
                        float k0 = dK[mtl * 8 + j * 4 + rh * 2 + 0] + bk2[j].x;
                        float k1 = dK[mtl * 8 + j * 4 + rh * 2 + 1] + bk2[j].y;
                        sp[mtl * 2 + rh] += k0 * qv.x + k1 * qv.y;
                    }
                }
            float p[4];
#pragma unroll
            for (int t = 0; t < 4; t++) {
                float s = sp[t];
                s += __shfl_xor_sync(0xffffffffu, s, 1);
                s += __shfl_xor_sync(0xffffffffu, s, 2);
                int gt = hf2 * 4 + ((t >> 1) << 1) + (t & 1);
                bool ok = (vm[gt] >> m) & 1u;
                float pv = __expf(ok ? s : -1e30f);
                p[t] = pv;
                den[gt] += pv;
            }
#pragma unroll
            for (int mtl = 0; mtl < 2; mtl++)
#pragma unroll
                for (int j = 0; j < 2; j++) {
                    int mt = hf2 * 2 + mtl;
#pragma unroll
                    for (int rh = 0; rh < 2; rh++) {
                        float pw = p[mtl * 2 + rh];
                        acc[(mt * 2 + j) * 4 + rh * 2 + 0] +=
                            pw * (dV[mtl * 8 + j * 4 + rh * 2 + 0] + bv2[j].x);
                        acc[(mt * 2 + j) * 4 + rh * 2 + 1] +=
                            pw * (dV[mtl * 8 + j * 4 + rh * 2 + 1] + bv2[j].y);
                    }
                }
        }

        if (i == 8 || i == 17) {
            __syncthreads();
            int dt = (i == 8) ? -1 : 1;
            stage_region(sb, hf, tbase + dt * 1024 - 33, tid);
            CPA_COMMIT();
        }
    }

    // ---- epilogue ----
#pragma unroll
    for (int mt = 0; mt < 4; mt++)
#pragma unroll
        for (int rh = 0; rh < 2; rh++) {
            int pos = tbase + (rg << 6) + l4 + (mt << 4) + (rh << 3);
            float iv = 1.0f / den[mt * 2 + rh];
            const float* rp = h_in + ((size_t)pos << 6);
            float* op = h_out + ((size_t)pos << 6);
#pragma unroll
            for (int j = 0; j < 2; j++) {
                int c = 16 * cg + 8 * j + 2 * tig;
                float2 r = *(const float2*)(rp + c);
                float ox = acc[(mt * 2 + j) * 4 + rh * 2 + 0] * iv + r.x;
                float oy = acc[(mt * 2 + j) * 4 + rh * 2 + 1] * iv + r.y;
                float2 o; o.x = ox; o.y = oy;
                *(float2*)(op + c) = o;
                if (hfo) {
                    __half2 h2 = __floats2half2_rn(ox, oy);
                    *(unsigned*)(&hfo[(size_t)pos * 64 + c]) = *(unsigned*)&h2;
                }
            }
        }
}

// ---------------------------------------------------------------------------
// 4) out = h @ W_out + b_out  (float4 smem fill)
// ---------------------------------------------------------------------------
__global__ void out_proj_kernel(const float* __restrict__ h,
                                const float* __restrict__ W_out,
                                const float* __restrict__ b_out,
                                float* __restrict__ out) {
    __shared__ float hs[32 * 64];
    int tid = threadIdx.x;
    int base = blockIdx.x * 32;
    for (int j = tid; j < 512; j += 128)
        *(float4*)&hs[j << 2] = *(const float4*)&h[(size_t)base * 64 + (j << 2)];
    __syncthreads();
    if (tid < 96) {
        int rr = tid / 3, f = tid - 3 * (tid / 3);
        float acc = b_out[f];
#pragma unroll 8
        for (int cp = 0; cp < 64; cp++)
            acc += hs[rr * 64 + cp] * W_out[cp * 3 + f];
        out[(base + rr) * 3 + f] = acc;
    }
}

// ---------------------------------------------------------------------------
extern "C" void kernel_launch(void* const* d_in, const int* in_sizes, int n_in,
                              void* d_out, int out_size) {
    const float* x     = (const float*)d_in[0];
    const float* W_in  = (const float*)d_in[1];
    const float* b_in  = (const float*)d_in[2];
    const float* W_out = (const float*)d_in[3];
    const float* b_out = (const float*)d_in[4];
    const float* Wq    = (const float*)d_in[5];
    const float* bq    = (const float*)d_in[6];
    const float* Wk    = (const float*)d_in[7];
    const float* bk    = (const float*)d_in[8];
    const float* Wv    = (const float*)d_in[9];
    const float* bv    = (const float*)d_in[10];
    float* out = (float*)d_out;

    float *h0, *h1;
    __half *hf0, *hf1;
    unsigned *wq_ph, *wkv_ph;
    cudaGetSymbolAddress((void**)&h0, g_h0);
    cudaGetSymbolAddress((void**)&h1, g_h1);
    cudaGetSymbolAddress((void**)&hf0, g_hf0);
    cudaGetSymbolAddress((void**)&hf1, g_hf1);
    cudaGetSymbolAddress((void**)&wq_ph, g_wq_ph);
    cudaGetSymbolAddress((void**)&wkv_ph, g_wkv_ph);
    cudaFuncSetAttribute(attn_kernel, cudaFuncAttributeMaxDynamicSharedMemorySize, SMEMB);

    prep_kernel<<<496, 256>>>(Wq, Wk, Wv, x);
    bn_fin_kernel<<<1, 32>>>();
    input_proj_kernel<<<(NQ * 16) / 256, 256>>>(x, W_in, b_in, h0, hf0);

    attn_kernel<<<256, 256, SMEMB>>>(h0, hf0, h1, hf1,
        wq_ph, bq, wkv_ph, bk, bv);
    attn_kernel<<<256, 256, SMEMB>>>(h1, hf1, h0, (__half*)nullptr,
        wq_ph + 2048, bq + 64, wkv_ph + 27 * 4096, bk + 27 * 64, bv + 27 * 64);

    out_proj_kernel<<<NQ / 32, 128>>>(h0, W_out, b_out, out);
}